// round 4
// baseline (speedup 1.0000x reference)
#include <cuda_runtime.h>
#include <math.h>

// Neural CDE (Tsit5, 511 steps) — 4 threads x 2 packed elements per pair,
// f32x2 FMA everywhere, interleaved bank-conflict-free smem layouts.

#define Hh     32
#define WIDw   64
#define W3R    96
#define CINc   3
#define Tt     512
#define NSTEPS 511
#define NTHR   128
#define NPAIR  32            // element-pairs per CTA
#define NELEM  64            // elements per CTA

// weight region offsets (floats)
#define OFF_W1 0
#define OFF_B1 (OFF_W1 + Hh*WIDw)        // 2048
#define OFF_W2 (OFF_B1 + WIDw)           // 2112
#define OFF_B2 (OFF_W2 + WIDw*WIDw)      // 6208
#define OFF_W3 (OFF_B2 + WIDw)           // 6272
#define OFF_B3 (OFF_W3 + WIDw*W3R)       // 12416
#define OFF_WEND (OFF_B3 + W3R)          // 12512 floats (50048 B, 16B aligned)

#define PSTRIDE 161                      // u64 per pair: Y32 + V1 64 + V2 64 + pad1
#define SMEM_FLOATS (OFF_WEND + NPAIR*PSTRIDE*2)
#define SMEM_BYTES  (SMEM_FLOATS * 4)    // 50048 + 41216 = 91264 -> 2 CTAs/SM

typedef unsigned long long u64;

// zero-padded Tsit5 A (row s holds coeffs for k_0..k_4; zeros beyond)
__constant__ float cA6[6][5] = {
    {0.f, 0.f, 0.f, 0.f, 0.f},
    {0.161f, 0.f, 0.f, 0.f, 0.f},
    {-0.008480655492356989f, 0.335480655492357f, 0.f, 0.f, 0.f},
    {2.8971530571054935f, -6.359448489975075f, 4.3622954328695815f, 0.f, 0.f},
    {5.325864828439257f, -11.748883564062828f, 7.4955393428898365f, -0.09249506636175525f, 0.f},
    {5.86145544294642f, -12.92096931784711f, 8.159367898576159f, -0.071584973281401f, -0.028269050394068383f}
};

__device__ __forceinline__ u64 pack2(float lo, float hi) {
    u64 r; asm("mov.b64 %0, {%1, %2};" : "=l"(r) : "f"(lo), "f"(hi)); return r;
}
__device__ __forceinline__ void unpack2(u64 v, float& lo, float& hi) {
    asm("mov.b64 {%0, %1}, %2;" : "=f"(lo), "=f"(hi) : "l"(v));
}
__device__ __forceinline__ u64 fma2(u64 a, u64 b, u64 c) {
    u64 d; asm("fma.rn.f32x2 %0, %1, %2, %3;" : "=l"(d) : "l"(a), "l"(b), "l"(c)); return d;
}
__device__ __forceinline__ u64 d2l(double x) { return __double_as_longlong(x); }

// output-index permutations (bank-conflict-free interleave)
__device__ __forceinline__ int jmap(int p)  {  // 64-wide: slot p -> logical j
    int q = p >> 4, s = (p >> 2) & 3, c = p & 3;
    return s*16 + q*4 + c;
}
__device__ __forceinline__ int j3map(int p) {  // 96-wide
    int q = p >> 4, s = (p >> 2) & 3, c = p & 3;
    return s*24 + q*4 + c;
}

// GEMM slice: NQ output-chunks (4 outs each) for 2 packed elements.
template<int NI, int NQ, int ROWF>
__device__ __forceinline__ void gemm_slice(const u64* __restrict__ act,
                                           const float* __restrict__ wbase,  // + sl*4 already
                                           const float* __restrict__ biasbase, // + sl*4 already
                                           u64* a01, u64* a23, u64* b01, u64* b23)
{
    #pragma unroll
    for (int q = 0; q < NQ; ++q) {
        u64 bv01 = *(const u64*)(biasbase + q*16);
        u64 bv23 = *(const u64*)(biasbase + q*16 + 2);
        a01[q] = bv01; a23[q] = bv23; b01[q] = bv01; b23[q] = bv23;
    }
    #pragma unroll 4
    for (int i = 0; i < NI; ++i) {
        float2 x = ((const float2*)act)[i];
        u64 xa = pack2(x.x, x.x);
        u64 xb = pack2(x.y, x.y);
        const float* wr = wbase + i*ROWF;
        #pragma unroll
        for (int q = 0; q < NQ; ++q) {
            double2 wd = *(const double2*)(wr + q*16);
            u64 w01 = d2l(wd.x), w23 = d2l(wd.y);
            a01[q] = fma2(w01, xa, a01[q]);
            a23[q] = fma2(w23, xa, a23[q]);
            b01[q] = fma2(w01, xb, b01[q]);
            b23[q] = fma2(w23, xb, b23[q]);
        }
    }
}

__global__ void __launch_bounds__(NTHR, 2)
ncde_kernel(const float* __restrict__ times,
            const float* __restrict__ grad,
            const float* __restrict__ w1, const float* __restrict__ b1,
            const float* __restrict__ w2, const float* __restrict__ b2,
            const float* __restrict__ w3, const float* __restrict__ b3,
            const float* __restrict__ w_enc, const float* __restrict__ b_enc,
            const float* __restrict__ w_ro, const float* __restrict__ b_ro,
            float* __restrict__ out, int Bn)
{
    extern __shared__ float sm[];
    const int tid = threadIdx.x;

    constexpr float TB[6] = {
        0.09646076681806523f, 0.01f, 0.4798896504144996f,
        1.379008574103742f, -3.290069515436081f, 2.324710524099774f
    };

    // ---- weight transposes into interleaved layouts ----
    for (int idx = tid; idx < Hh*WIDw; idx += NTHR) {
        int i = idx >> 6, p = idx & 63;
        sm[OFF_W1 + i*WIDw + p] = w1[jmap(p)*Hh + i];
    }
    for (int p = tid; p < WIDw; p += NTHR) sm[OFF_B1 + p] = b1[jmap(p)];
    for (int idx = tid; idx < WIDw*WIDw; idx += NTHR) {
        int ip = idx >> 6, p = idx & 63;
        sm[OFF_W2 + ip*WIDw + p] = w2[jmap(p)*WIDw + jmap(ip)];
    }
    for (int p = tid; p < WIDw; p += NTHR) sm[OFF_B2 + p] = b2[jmap(p)];
    for (int idx = tid; idx < WIDw*W3R; idx += NTHR) {
        int ip = idx / W3R, p = idx % W3R;
        sm[OFF_W3 + ip*W3R + p] = w3[j3map(p)*WIDw + jmap(ip)];
    }
    for (int p = tid; p < W3R; p += NTHR) sm[OFF_B3 + p] = b3[j3map(p)];
    __syncthreads();

    const int lane = tid & 31;
    const int sl   = lane >> 3;          // output slice 0..3
    const int e    = lane & 7;
    const int warp = tid >> 5;
    const int pr   = warp*8 + e;         // pair index 0..31

    u64* stp = (u64*)(sm + OFF_WEND) + pr * PSTRIDE;
    u64* Yp  = stp;                      // 32 dims
    u64* V1p = stp + 32;                 // 64
    u64* V2p = stp + 96;                 // 64

    const int  b0 = blockIdx.x * NELEM + 2*pr;
    const int  b1i = b0 + 1;
    const int  bb0 = (b0  < Bn) ? b0  : (Bn - 1);
    const int  bb1 = (b1i < Bn) ? b1i : (Bn - 1);

    const float dt = times[1] - times[0];
    const float* gpA = grad + (size_t)bb0 * (Tt * CINc);
    const float* gpB = grad + (size_t)bb1 * (Tt * CINc);

    // packed Tsit5 state
    u64 z[8], kst[6][8];
    #pragma unroll
    for (int j = 0; j < 8; ++j) {
        float v = w_enc[8*sl + j] + b_enc[8*sl + j];
        z[j] = pack2(v, v);
    }
    #pragma unroll
    for (int p = 0; p < 6; ++p)
        #pragma unroll
        for (int j = 0; j < 8; ++j) kst[p][j] = pack2(0.f, 0.f);

    u64 cB2[6];
    #pragma unroll
    for (int p = 0; p < 6; ++p) cB2[p] = pack2(TB[p], TB[p]);

    const float* w1b = sm + OFF_W1 + sl*4;
    const float* w2b = sm + OFF_W2 + sl*4;
    const float* w3b = sm + OFF_W3 + sl*4;
    const float* b1b = sm + OFF_B1 + sl*4;
    const float* b2b = sm + OFF_B2 + sl*4;
    const float* b3b = sm + OFF_B3 + sl*4;

    float gA0 = gpA[0], gA1 = gpA[1], gA2 = gpA[2];
    float gB0 = gpB[0], gB1 = gpB[1], gB2 = gpB[2];

    #pragma unroll 1
    for (int n = 0; n < NSTEPS; ++n) {
        const float dqA[3] = {gA0*dt, gA1*dt, gA2*dt};
        const float dqB[3] = {gB0*dt, gB1*dt, gB2*dt};
        if (n + 1 < NSTEPS) {
            const float* ga = gpA + (n+1)*3; gA0 = ga[0]; gA1 = ga[1]; gA2 = ga[2];
            const float* gb = gpB + (n+1)*3; gB0 = gb[0]; gB1 = gb[1]; gB2 = gb[2];
        }

        #pragma unroll 1
        for (int sg = 0; sg < 6; ++sg) {
            // ---- stage combine: Y = z + sum_p A[sg][p] k_p (own 8 dims) ----
            u64 cc[5];
            #pragma unroll
            for (int p = 0; p < 5; ++p) { float c = cA6[sg][p]; cc[p] = pack2(c, c); }
            #pragma unroll
            for (int j = 0; j < 8; ++j) {
                u64 y = z[j];
                #pragma unroll
                for (int p = 0; p < 5; ++p) y = fma2(cc[p], kst[p][j], y);
                Yp[8*sl + j] = y;
            }
            __syncwarp();

            u64 a01[6], a23[6], b01[6], b23[6];

            // ---- layer 1 ----
            gemm_slice<Hh, 4, WIDw>(Yp, w1b, b1b, a01, a23, b01, b23);
            #pragma unroll
            for (int q = 0; q < 4; ++q) {
                float f0A,f1A,f2A,f3A, f0B,f1B,f2B,f3B;
                unpack2(a01[q], f0A, f1A); unpack2(b01[q], f0B, f1B);
                unpack2(a23[q], f2A, f3A); unpack2(b23[q], f2B, f3B);
                u64* dst = V1p + q*16 + sl*4;
                dst[0] = pack2(tanhf(f0A), tanhf(f0B));
                dst[1] = pack2(tanhf(f1A), tanhf(f1B));
                dst[2] = pack2(tanhf(f2A), tanhf(f2B));
                dst[3] = pack2(tanhf(f3A), tanhf(f3B));
            }
            __syncwarp();

            // ---- layer 2 ----
            gemm_slice<WIDw, 4, WIDw>(V1p, w2b, b2b, a01, a23, b01, b23);
            #pragma unroll
            for (int q = 0; q < 4; ++q) {
                float f0A,f1A,f2A,f3A, f0B,f1B,f2B,f3B;
                unpack2(a01[q], f0A, f1A); unpack2(b01[q], f0B, f1B);
                unpack2(a23[q], f2A, f3A); unpack2(b23[q], f2B, f3B);
                u64* dst = V2p + q*16 + sl*4;
                dst[0] = pack2(tanhf(f0A), tanhf(f0B));
                dst[1] = pack2(tanhf(f1A), tanhf(f1B));
                dst[2] = pack2(tanhf(f2A), tanhf(f2B));
                dst[3] = pack2(tanhf(f3A), tanhf(f3B));
            }
            __syncwarp();

            // ---- layer 3 + dq contraction ----
            gemm_slice<WIDw, 6, W3R>(V2p, w3b, b3b, a01, a23, b01, b23);
            float uA[24], uB[24];
            #pragma unroll
            for (int q = 0; q < 6; ++q) {
                unpack2(a01[q], uA[4*q+0], uA[4*q+1]);
                unpack2(a23[q], uA[4*q+2], uA[4*q+3]);
                unpack2(b01[q], uB[4*q+0], uB[4*q+1]);
                unpack2(b23[q], uB[4*q+2], uB[4*q+3]);
            }
            float kA[8], kB[8];
            #pragma unroll
            for (int h = 0; h < 8; ++h) { kA[h] = 0.f; kB[h] = 0.f; }
            #pragma unroll
            for (int p3 = 0; p3 < 24; ++p3) {
                const int h = p3 / 3, ch = p3 % 3;
                kA[h] = fmaf(uA[p3], dqA[ch], kA[h]);
                kB[h] = fmaf(uB[p3], dqB[ch], kB[h]);
            }
            #pragma unroll
            for (int p = 0; p < 6; ++p)
                if (p == sg) {
                    #pragma unroll
                    for (int h = 0; h < 8; ++h) kst[p][h] = pack2(kA[h], kB[h]);
                }
        }

        // ---- z += sum_p B[p] k_p ----
        #pragma unroll
        for (int j = 0; j < 8; ++j) {
            u64 zz = z[j];
            #pragma unroll
            for (int p = 0; p < 6; ++p) zz = fma2(cB2[p], kst[p][j], zz);
            z[j] = zz;
        }
    }

    // ---- readout ----
    float pA = 0.f, pB = 0.f;
    #pragma unroll
    for (int j = 0; j < 8; ++j) {
        float za, zb; unpack2(z[j], za, zb);
        const float wr = w_ro[8*sl + j];
        pA = fmaf(za, wr, pA);
        pB = fmaf(zb, wr, pB);
    }
    pA += __shfl_xor_sync(0xffffffffu, pA, 8);
    pA += __shfl_xor_sync(0xffffffffu, pA, 16);
    pB += __shfl_xor_sync(0xffffffffu, pB, 8);
    pB += __shfl_xor_sync(0xffffffffu, pB, 16);
    if (sl == 0) {
        const float br = b_ro[0];
        if (b0  < Bn) out[b0]  = 1.0f / (1.0f + expf(-(pA + br)));
        if (b1i < Bn) out[b1i] = 1.0f / (1.0f + expf(-(pB + br)));
    }
}

extern "C" void kernel_launch(void* const* d_in, const int* in_sizes, int n_in,
                              void* d_out, int out_size)
{
    const float* times = (const float*)d_in[0];
    const float* grad  = (const float*)d_in[1];
    const float* w1    = (const float*)d_in[2];
    const float* b1    = (const float*)d_in[3];
    const float* w2    = (const float*)d_in[4];
    const float* b2    = (const float*)d_in[5];
    const float* w3    = (const float*)d_in[6];
    const float* b3    = (const float*)d_in[7];
    const float* w_enc = (const float*)d_in[8];
    const float* b_enc = (const float*)d_in[9];
    const float* w_ro  = (const float*)d_in[10];
    const float* b_ro  = (const float*)d_in[11];
    float* out = (float*)d_out;

    const int Bn = in_sizes[1] / (Tt * CINc);
    const int nblocks = (Bn + NELEM - 1) / NELEM;

    cudaFuncSetAttribute(ncde_kernel,
                         cudaFuncAttributeMaxDynamicSharedMemorySize,
                         (int)SMEM_BYTES);
    ncde_kernel<<<nblocks, NTHR, SMEM_BYTES>>>(
        times, grad, w1, b1, w2, b2, w3, b3, w_enc, b_enc, w_ro, b_ro, out, Bn);
}

// round 6
// speedup vs baseline: 2.5135x; 2.5135x over previous
#include <cuda_runtime.h>
#include <cuda_fp16.h>
#include <math.h>

typedef unsigned int u32;

#define NSTEPS 511
#define Tt     512
#define NTHR   256
#define MROWS  128

// ---- smem byte offsets ----
#define SM_W1 0            // 16 tiles * 512B
#define SM_W2 8192         // 32 tiles
#define SM_W3 24576        // 48 tiles
#define SM_B1 49152        // f32[64]
#define SM_B2 49408        // f32[64]
#define SM_B3 49664        // f32[96] (permuted)
#define SM_KST 50048       // f32[6][16][NTHR]
#define SMEM_BYTES (SM_KST + 6*16*NTHR*4)   // 148,352 B

__constant__ float cA6[6][5] = {
    {0.f,0.f,0.f,0.f,0.f},
    {0.161f,0.f,0.f,0.f,0.f},
    {-0.008480655492356989f,0.335480655492357f,0.f,0.f,0.f},
    {2.8971530571054935f,-6.359448489975075f,4.3622954328695815f,0.f,0.f},
    {5.325864828439257f,-11.748883564062828f,7.4955393428898365f,-0.09249506636175525f,0.f},
    {5.86145544294642f,-12.92096931784711f,8.159367898576159f,-0.071584973281401f,-0.028269050394068383f}};
__constant__ float cBt[6] = {
    0.09646076681806523f,0.01f,0.4798896504144996f,
    1.379008574103742f,-3.290069515436081f,2.324710524099774f};

// physical A-col p (0..31) -> logical h index
__device__ __forceinline__ int hphys(int p){
    return 8*((p&7)>>1) + 2*(p>>3) + (p&1);
}
// physical L3 out col p3 (0..95) -> logical w3 row (3h+c)
__device__ __forceinline__ int w3row(int p3){
    int j = p3>>3, r = p3&7, tg = r>>1, e = r&1;
    int q = 2*j + e, d = q/3, c = q%3;
    return 3*(8*tg + d) + c;
}

__device__ __forceinline__ u32 h2p(float x, float y){
    return (u32)__half_as_ushort(__float2half_rn(x))
         | ((u32)__half_as_ushort(__float2half_rn(y)) << 16);
}
__device__ __forceinline__ void split2(float x, float y, u32& hi, u32& lo){
    __half hx = __float2half_rn(x), hy = __float2half_rn(y);
    hi = (u32)__half_as_ushort(hx) | ((u32)__half_as_ushort(hy) << 16);
    lo = h2p(x - __half2float(hx), y - __half2float(hy));
}

__device__ __forceinline__ void mma16816(float* c, const u32* a, u32 b0, u32 b1){
    asm("mma.sync.aligned.m16n8k16.row.col.f32.f16.f16.f32 "
        "{%0,%1,%2,%3}, {%4,%5,%6,%7}, {%8,%9}, {%0,%1,%2,%3};"
        : "+f"(c[0]), "+f"(c[1]), "+f"(c[2]), "+f"(c[3])
        : "r"(a[0]), "r"(a[1]), "r"(a[2]), "r"(a[3]), "r"(b0), "r"(b1));
}

// NJ n-tiles, NT k-tiles; bias init; 3-term split accumulate
template<int NJ, int NT>
__device__ __forceinline__ void runLayer(const u32* __restrict__ tiles,
                                         const float* __restrict__ bias,
                                         const u32 (*ah)[4], const u32 (*al)[4],
                                         float (*C)[4], int lane, int tg)
{
    #pragma unroll
    for (int j=0;j<NJ;++j){
        float2 bb = *(const float2*)(bias + 8*j + 2*tg);
        C[j][0]=bb.x; C[j][1]=bb.y; C[j][2]=bb.x; C[j][3]=bb.y;
    }
    #pragma unroll
    for (int j=0;j<NJ;++j){
        #pragma unroll
        for (int t=0;t<NT;++t){
            uint4 w = *(const uint4*)(tiles + (j*NT+t)*128 + lane*4);
            mma16816(C[j], ah[t], w.x, w.y);   // Ah*Bh
            mma16816(C[j], al[t], w.x, w.y);   // Al*Bh
            mma16816(C[j], ah[t], w.z, w.w);   // Ah*Bl
        }
    }
}

// tanh + hi/lo split: C n-tile pair (2t,2t+1) -> A k-tile t
template<int NTo>
__device__ __forceinline__ void actSplit(const float (*C)[4], u32 (*ah)[4], u32 (*al)[4]){
    #pragma unroll
    for (int t=0;t<NTo;++t){
        split2(tanhf(C[2*t][0]),   tanhf(C[2*t][1]),   ah[t][0], al[t][0]);
        split2(tanhf(C[2*t][2]),   tanhf(C[2*t][3]),   ah[t][1], al[t][1]);
        split2(tanhf(C[2*t+1][0]), tanhf(C[2*t+1][1]), ah[t][2], al[t][2]);
        split2(tanhf(C[2*t+1][2]), tanhf(C[2*t+1][3]), ah[t][3], al[t][3]);
    }
}

__global__ void __launch_bounds__(NTHR, 1)
ncde_mma(const float* __restrict__ times, const float* __restrict__ grad,
         const float* __restrict__ w1, const float* __restrict__ pb1,
         const float* __restrict__ w2, const float* __restrict__ pb2,
         const float* __restrict__ w3, const float* __restrict__ pb3,
         const float* __restrict__ w_enc, const float* __restrict__ b_enc,
         const float* __restrict__ w_ro, const float* __restrict__ b_ro,
         float* __restrict__ out, int Bn)
{
    extern __shared__ float sm[];
    char* smc = (char*)sm;
    u32* tw1 = (u32*)(smc + SM_W1);
    u32* tw2 = (u32*)(smc + SM_W2);
    u32* tw3 = (u32*)(smc + SM_W3);
    float* b1s = (float*)(smc + SM_B1);
    float* b2s = (float*)(smc + SM_B2);
    float* b3s = (float*)(smc + SM_B3);
    float* kbuf = (float*)(smc + SM_KST);

    const int tid = threadIdx.x, warp = tid>>5, lane = tid&31;
    const int g = lane>>2, tg = lane&3;

    // ---- build weight fragment tiles (hi/lo f16) ----
    // L1: W1[64 out][32 in], input cols permuted by hphys. tiles (j*2+t)
    for (int s = tid; s < 16*32; s += NTHR){
        int tile = s>>5, l = s&31;
        int j = tile>>1, t = tile&1;
        int gg = l>>2, tt = l&3;
        int n = 8*j+gg, k0 = 16*t+2*tt;
        float f0 = w1[n*32 + hphys(k0)],   f1 = w1[n*32 + hphys(k0+1)];
        float f8 = w1[n*32 + hphys(k0+8)], f9 = w1[n*32 + hphys(k0+9)];
        u32 h01,l01,h89,l89;
        split2(f0,f1,h01,l01); split2(f8,f9,h89,l89);
        u32* d = tw1 + tile*128 + l*4;
        d[0]=h01; d[1]=h89; d[2]=l01; d[3]=l89;
    }
    // L2: W2[64][64], tiles (j*4+t)
    for (int s = tid; s < 32*32; s += NTHR){
        int tile = s>>5, l = s&31;
        int j = tile>>2, t = tile&3;
        int gg = l>>2, tt = l&3;
        int n = 8*j+gg, k0 = 16*t+2*tt;
        float f0 = w2[n*64+k0],   f1 = w2[n*64+k0+1];
        float f8 = w2[n*64+k0+8], f9 = w2[n*64+k0+9];
        u32 h01,l01,h89,l89;
        split2(f0,f1,h01,l01); split2(f8,f9,h89,l89);
        u32* d = tw2 + tile*128 + l*4;
        d[0]=h01; d[1]=h89; d[2]=l01; d[3]=l89;
    }
    // L3: W3[96][64], rows permuted by w3row. tiles (j*4+t)
    for (int s = tid; s < 48*32; s += NTHR){
        int tile = s>>5, l = s&31;
        int j = tile>>2, t = tile&3;
        int gg = l>>2, tt = l&3;
        int n = 8*j+gg, k0 = 16*t+2*tt;
        int rr = w3row(n);
        float f0 = w3[rr*64+k0],   f1 = w3[rr*64+k0+1];
        float f8 = w3[rr*64+k0+8], f9 = w3[rr*64+k0+9];
        u32 h01,l01,h89,l89;
        split2(f0,f1,h01,l01); split2(f8,f9,h89,l89);
        u32* d = tw3 + tile*128 + l*4;
        d[0]=h01; d[1]=h89; d[2]=l01; d[3]=l89;
    }
    if (tid < 64) b1s[tid] = pb1[tid];
    if (tid < 64) b2s[tid] = pb2[tid];
    if (tid < 96) b3s[tid] = pb3[w3row(tid)];
    __syncthreads();

    // ---- per-thread state: rows g and g+8 of warp's 16-row block ----
    const int base = blockIdx.x*MROWS + warp*16;
    const int rowg = base + g, rowh = rowg + 8;
    const int rgc = (rowg < Bn) ? rowg : (Bn-1);
    const int rhc = (rowh < Bn) ? rowh : (Bn-1);
    const float dt = times[1] - times[0];
    const float* gA = grad + (size_t)rgc * (Tt*3);
    const float* gB = grad + (size_t)rhc * (Tt*3);

    float zg[8], zh[8];
    #pragma unroll
    for (int d=0; d<8; ++d){
        float v = w_enc[8*tg+d] + b_enc[8*tg+d];
        zg[d] = v; zh[d] = v;
    }

    #pragma unroll 1
    for (int n=0; n<NSTEPS; ++n){
        float dqg[3], dqh[3];
        #pragma unroll
        for (int c=0;c<3;++c){ dqg[c] = gA[n*3+c]*dt; dqh[c] = gB[n*3+c]*dt; }

        #pragma unroll 1
        for (int sg=0; sg<6; ++sg){
            // ---- stage combine: Y = z + sum_p A[sg][p] k_p ----
            float Yg[8], Yh[8];
            #pragma unroll
            for (int d=0;d<8;++d){ Yg[d]=zg[d]; Yh[d]=zh[d]; }
            for (int p=0;p<sg;++p){
                const float c = cA6[sg][p];
                #pragma unroll
                for (int d=0;d<8;++d){
                    Yg[d] = fmaf(c, kbuf[(p*16+d)*NTHR+tid],   Yg[d]);
                    Yh[d] = fmaf(c, kbuf[(p*16+8+d)*NTHR+tid], Yh[d]);
                }
            }
            u32 yah[2][4], yal[2][4];
            #pragma unroll
            for (int t=0;t<2;++t){
                split2(Yg[4*t],   Yg[4*t+1], yah[t][0], yal[t][0]);
                split2(Yh[4*t],   Yh[4*t+1], yah[t][1], yal[t][1]);
                split2(Yg[4*t+2], Yg[4*t+3], yah[t][2], yal[t][2]);
                split2(Yh[4*t+2], Yh[4*t+3], yah[t][3], yal[t][3]);
            }

            // ---- L1 ----
            float C1[8][4];
            runLayer<8,2>(tw1, b1s, yah, yal, C1, lane, tg);
            u32 a2h[4][4], a2l[4][4];
            actSplit<4>(C1, a2h, a2l);

            // ---- L2 ----
            float C2[8][4];
            runLayer<8,4>(tw2, b2s, a2h, a2l, C2, lane, tg);
            u32 a3h[4][4], a3l[4][4];
            actSplit<4>(C2, a3h, a3l);

            // ---- L3 ----
            float C3[12][4];
            runLayer<12,4>(tw3, b3s, a3h, a3l, C3, lane, tg);

            // ---- dq contraction -> k (this thread's 8 h-dims, both rows) ----
            float nkg[8], nkh[8];
            #pragma unroll
            for (int d=0;d<8;++d){ nkg[d]=0.f; nkh[d]=0.f; }
            #pragma unroll
            for (int j=0;j<12;++j){
                #pragma unroll
                for (int e=0;e<2;++e){
                    const int q = 2*j+e, d = q/3, c = q%3;
                    nkg[d] = fmaf(C3[j][e],   dqg[c], nkg[d]);
                    nkh[d] = fmaf(C3[j][2+e], dqh[c], nkh[d]);
                }
            }
            #pragma unroll
            for (int d=0;d<8;++d){
                kbuf[(sg*16+d)*NTHR+tid]   = nkg[d];
                kbuf[(sg*16+8+d)*NTHR+tid] = nkh[d];
            }
        }

        // ---- z += sum_p B[p] k_p ----
        #pragma unroll
        for (int p=0;p<6;++p){
            const float c = cBt[p];
            #pragma unroll
            for (int d=0;d<8;++d){
                zg[d] = fmaf(c, kbuf[(p*16+d)*NTHR+tid],   zg[d]);
                zh[d] = fmaf(c, kbuf[(p*16+8+d)*NTHR+tid], zh[d]);
            }
        }
    }

    // ---- readout: logit = z . w_ro (reduce over tg quad) ----
    float pg = 0.f, ph = 0.f;
    #pragma unroll
    for (int d=0;d<8;++d){
        const float wv = w_ro[8*tg+d];
        pg = fmaf(zg[d], wv, pg);
        ph = fmaf(zh[d], wv, ph);
    }
    pg += __shfl_xor_sync(0xffffffffu, pg, 1);
    pg += __shfl_xor_sync(0xffffffffu, pg, 2);
    ph += __shfl_xor_sync(0xffffffffu, ph, 1);
    ph += __shfl_xor_sync(0xffffffffu, ph, 2);
    if (tg == 0){
        const float br = b_ro[0];
        if (rowg < Bn) out[rowg] = 1.0f/(1.0f + expf(-(pg + br)));
        if (rowh < Bn) out[rowh] = 1.0f/(1.0f + expf(-(ph + br)));
    }
}

extern "C" void kernel_launch(void* const* d_in, const int* in_sizes, int n_in,
                              void* d_out, int out_size)
{
    const float* times=(const float*)d_in[0];
    const float* grad =(const float*)d_in[1];
    const float* w1=(const float*)d_in[2];  const float* b1=(const float*)d_in[3];
    const float* w2=(const float*)d_in[4];  const float* b2=(const float*)d_in[5];
    const float* w3=(const float*)d_in[6];  const float* b3=(const float*)d_in[7];
    const float* we=(const float*)d_in[8];  const float* be=(const float*)d_in[9];
    const float* wr=(const float*)d_in[10]; const float* br=(const float*)d_in[11];
    float* out=(float*)d_out;

    const int Bn = in_sizes[1] / (Tt*3);
    const int nblocks = (Bn + MROWS - 1) / MROWS;

    cudaFuncSetAttribute(ncde_mma, cudaFuncAttributeMaxDynamicSharedMemorySize,
                         (int)SMEM_BYTES);
    ncde_mma<<<nblocks, NTHR, SMEM_BYTES>>>(
        times, grad, w1, b1, w2, b2, w3, b3, we, be, wr, br, out, Bn);
}